// round 7
// baseline (speedup 1.0000x reference)
#include <cuda_runtime.h>
#include <math.h>

#define Bb   64
#define Nn   256
#define Mm   16
#define ONF_ 92
#define KE   41      // OEF
#define NFD  128
#define EFD  64

// ---------------- scratch (static device globals; no allocs) ----------------
__device__ float g_nfA[Bb*Nn*NFD];                 // 8.4 MB
__device__ float g_nfB[Bb*Nn*NFD];                 // 8.4 MB
__device__ float g_SG[(size_t)Bb*Nn*512];          // 33.5 MB  (S at [0,256), G at [256,512))
__device__ float g_WfoldT[3*KE*256];               // folded edge weights, k-major [41][256] per conv
__device__ float g_bfold[3*256];                   // folded bias per conv

__device__ __forceinline__ float softplusf_(float x) {
    return (x > 20.f) ? x : log1pf(__expf(x));
}
__device__ __forceinline__ float sigmoidf_(float x) {
    return __fdividef(1.f, 1.f + __expf(-x));
}

// ---------------- weight fold: WfoldT[k][o] = sum_j W[o][256+j]*We[j][k] ----
__global__ void fold_kernel(const float* __restrict__ We,   // [64][41]
                            const float* __restrict__ be,   // [64]
                            const float* __restrict__ W,    // [256][320]
                            const float* __restrict__ b,    // [256]
                            float* __restrict__ WfoldT,     // [41][256]
                            float* __restrict__ bfold)      // [256]
{
    __shared__ float Wes[EFD][KE];
    __shared__ float bes[EFD];
    int tid = threadIdx.x;   // 256
    for (int i = tid; i < EFD*KE; i += 256) Wes[i/KE][i%KE] = We[i];
    if (tid < EFD) bes[tid] = be[tid];
    __syncthreads();

    int o = tid;
    const float* wr = &W[o*320 + 256];
    float bf = b[o];
    #pragma unroll 4
    for (int j = 0; j < EFD; j++) bf += wr[j] * bes[j];
    bfold[o] = bf;
    for (int k = 0; k < KE; k++) {
        float s = 0.f;
        #pragma unroll 4
        for (int j = 0; j < EFD; j++) s += wr[j] * Wes[j][k];
        WfoldT[k*256 + o] = s;
    }
}

// ---------------- generic fp32 GEMM: C[r][o] = sum_k X[r][k]*W[o][k] + b[o] -
// block tile 64x64, 256 threads, 4x4 microtile, K-chunk 16.
// R and O must be multiples of 64; K arbitrary.
__global__ __launch_bounds__(256) void gemm64_kernel(
    const float* __restrict__ X, int ldx,
    const float* __restrict__ W, int ldw,
    const float* __restrict__ bias,
    float* __restrict__ C, int ldc, int K)
{
    __shared__ float Xs[16][64];
    __shared__ float Ws[16][64];
    int tid = threadIdx.x;
    int rb = blockIdx.y * 64, ob = blockIdx.x * 64;
    int lr = tid >> 2;            // 0..63
    int lk = (tid & 3) * 4;       // 0,4,8,12
    int tr = tid >> 4;            // 0..15
    int tc = tid & 15;            // 0..15

    float acc[4][4];
    #pragma unroll
    for (int i = 0; i < 4; i++)
        #pragma unroll
        for (int j = 0; j < 4; j++) acc[i][j] = 0.f;

    for (int kb = 0; kb < K; kb += 16) {
        #pragma unroll
        for (int j = 0; j < 4; j++) {
            int k = kb + lk + j;
            Xs[lk+j][lr] = (k < K) ? X[(size_t)(rb + lr) * ldx + k] : 0.f;
            Ws[lk+j][lr] = (k < K) ? W[(size_t)(ob + lr) * ldw + k] : 0.f;
        }
        __syncthreads();
        #pragma unroll
        for (int kk = 0; kk < 16; kk++) {
            float4 xv = *(const float4*)&Xs[kk][4*tr];
            float4 wv = *(const float4*)&Ws[kk][4*tc];
            acc[0][0] += xv.x*wv.x; acc[0][1] += xv.x*wv.y; acc[0][2] += xv.x*wv.z; acc[0][3] += xv.x*wv.w;
            acc[1][0] += xv.y*wv.x; acc[1][1] += xv.y*wv.y; acc[1][2] += xv.y*wv.z; acc[1][3] += xv.y*wv.w;
            acc[2][0] += xv.z*wv.x; acc[2][1] += xv.z*wv.y; acc[2][2] += xv.z*wv.z; acc[2][3] += xv.z*wv.w;
            acc[3][0] += xv.w*wv.x; acc[3][1] += xv.w*wv.y; acc[3][2] += xv.w*wv.z; acc[3][3] += xv.w*wv.w;
        }
        __syncthreads();
    }
    float4 bb = make_float4(0.f, 0.f, 0.f, 0.f);
    if (bias) bb = *(const float4*)&bias[ob + 4*tc];
    #pragma unroll
    for (int i = 0; i < 4; i++) {
        float4 v = make_float4(acc[i][0] + bb.x, acc[i][1] + bb.y,
                               acc[i][2] + bb.z, acc[i][3] + bb.w);
        *(float4*)&C[(size_t)(rb + 4*tr + i) * ldc + ob + 4*tc] = v;
    }
}

// ---------------- fused edge conv kernel -----------------------------------
// block: 8 nodes of one batch = 128 edges. dyn smem: WT[41][256], Et[41][128],
// bias[256], idx[128]. Per thread: 8 edges x (4 filter outs, 4 core outs).
__global__ __launch_bounds__(256) void edge_conv_kernel(
    const float* __restrict__ edge_fea,  // [B,N,M,41]
    const int*   __restrict__ eidx,      // [B,N,M]
    const float* __restrict__ SG,        // [B,N,512]
    const float* __restrict__ WfoldT,    // [41][256]
    const float* __restrict__ bfold,     // [256]
    const float* __restrict__ nf_in,     // [B,N,128]
    const float* __restrict__ alpha_p,
    float* __restrict__ nf_out)          // [B,N,128]
{
    extern __shared__ float smem[];
    float* WT  = smem;                    // 41*256
    float* Et  = smem + KE*256;           // 41*128
    float* bia = Et + KE*128;             // 256
    int*   nbs = (int*)(bia + 256);       // 128

    int tid = threadIdx.x;
    int b   = blockIdx.y;
    int n0  = blockIdx.x * 8;
    int bn0 = b * Nn + n0;

    for (int i = tid; i < KE*256; i += 256) WT[i] = WfoldT[i];
    bia[tid] = bfold[tid];
    if (tid < 128) nbs[tid] = eidx[bn0 * Mm + tid];
    {
        const float* ep = edge_fea + (size_t)bn0 * Mm * KE;
        for (int i = tid; i < 128*KE; i += 256) {
            int e = i / KE, k = i - e * KE;
            Et[k*128 + e] = ep[i];
        }
    }
    __syncthreads();

    float alpha = *alpha_p;
    int half = tid & 1;
    int pg   = (tid >> 1) & 31;
    int tlb  = tid >> 6;          // 0..3
    int o0   = pg * 4;

    for (int p = 0; p < 2; p++) {
        int tl = tlb + 4*p;            // node within block 0..7
        int e0 = tl*16 + half*8;       // first of this thread's 8 edges

        // prefetch neighbor ids for this edge group
        int nbr[8];
        #pragma unroll
        for (int j = 0; j < 8; j++) nbr[j] = nbs[e0 + j];

        float acc[8][8];
        #pragma unroll
        for (int j = 0; j < 8; j++)
            #pragma unroll
            for (int q = 0; q < 8; q++) acc[j][q] = 0.f;

        #pragma unroll 1
        for (int k = 0; k < KE; k++) {
            const float* er = &Et[k*128 + e0];
            float4 xa = *(const float4*)er;
            float4 xb = *(const float4*)(er + 4);
            const float* wr = &WT[k*256 + o0];
            float4 wa = *(const float4*)wr;          // filter outs o0..o0+3
            float4 wb = *(const float4*)(wr + 128);  // core outs o0+128..
            float xs[8], ws[8];
            xs[0]=xa.x; xs[1]=xa.y; xs[2]=xa.z; xs[3]=xa.w;
            xs[4]=xb.x; xs[5]=xb.y; xs[6]=xb.z; xs[7]=xb.w;
            ws[0]=wa.x; ws[1]=wa.y; ws[2]=wa.z; ws[3]=wa.w;
            ws[4]=wb.x; ws[5]=wb.y; ws[6]=wb.z; ws[7]=wb.w;
            #pragma unroll
            for (int j = 0; j < 8; j++)
                #pragma unroll
                for (int q = 0; q < 8; q++)
                    acc[j][q] += xs[j] * ws[q];
        }

        int bn = b * Nn + (n0 + tl);
        const float* Srow = SG + (size_t)bn * 512;
        float4 Sa = *(const float4*)&Srow[o0];
        float4 Sc = *(const float4*)&Srow[o0 + 128];
        float4 ba = *(const float4*)&bia[o0];
        float4 bc = *(const float4*)&bia[o0 + 128];
        float sf[4] = {Sa.x + ba.x, Sa.y + ba.y, Sa.z + ba.z, Sa.w + ba.w};
        float sc[4] = {Sc.x + bc.x, Sc.y + bc.y, Sc.z + bc.z, Sc.w + bc.w};

        float sums[4] = {0.f, 0.f, 0.f, 0.f};
        #pragma unroll
        for (int j = 0; j < 8; j++) {
            int nb = nbr[j];
            float mask = (nb >= 0) ? 1.f : 0.f;
            if (nb < 0) nb = 0;
            const float* Grow = SG + ((size_t)(b * Nn + nb)) * 512 + 256;
            float4 Ga = *(const float4*)&Grow[o0];
            float4 Gc = *(const float4*)&Grow[o0 + 128];
            float gaf[4] = {Ga.x, Ga.y, Ga.z, Ga.w};
            float gcf[4] = {Gc.x, Gc.y, Gc.z, Gc.w};
            #pragma unroll
            for (int q = 0; q < 4; q++) {
                float gf = acc[j][q]     + sf[q] + gaf[q];
                float gc = acc[j][q + 4] + sc[q] + gcf[q];
                float filt = mask * sigmoidf_(gf);
                float core = softplusf_(gc);
                sums[q] += filt * core;
            }
        }
        // combine the two m-halves (partner is tid^1, same warp)
        #pragma unroll
        for (int q = 0; q < 4; q++)
            sums[q] += __shfl_xor_sync(0xffffffffu, sums[q], 1);

        if (half == 0) {
            const float* nin = nf_in + (size_t)bn * NFD + o0;
            float4 nv = *(const float4*)nin;
            float4 ov;
            ov.x = softplusf_(alpha * nv.x + sums[0]);
            ov.y = softplusf_(alpha * nv.y + sums[1]);
            ov.z = softplusf_(alpha * nv.z + sums[2]);
            ov.w = softplusf_(alpha * nv.w + sums[3]);
            *(float4*)&nf_out[(size_t)bn * NFD + o0] = ov;
        }
    }
}

// ---------------- final: node1 = sigmoid(DAw*dis+DAb) @ fin ----------------
// out[...,:64] already holds fin (written by gemm64). This writes out[...,64:].
__global__ __launch_bounds__(256) void final_mix_kernel(
    const float* __restrict__ dis,
    const float* __restrict__ DAw_p,
    const float* __restrict__ DAb_p,
    float* __restrict__ out)
{
    __shared__ float DAs[16][256];
    int b  = blockIdx.y;
    int i0 = blockIdx.x * 16;
    float daw = *DAw_p, dab = *DAb_p;
    for (int t = threadIdx.x; t < 16*256; t += 256) {
        int ii = t >> 8, j = t & 255;
        DAs[ii][j] = sigmoidf_(daw * dis[(i0 + ii) * Nn + j] + dab);
    }
    __syncthreads();

    int f = threadIdx.x & 63;
    int g = threadIdx.x >> 6;   // 0..3
    float acc[4] = {0.f, 0.f, 0.f, 0.f};
    const float* fin = out + (size_t)b * Nn * 128;
    for (int j = 0; j < Nn; j++) {
        float x = fin[(size_t)j * 128 + f];
        #pragma unroll
        for (int r = 0; r < 4; r++) acc[r] += DAs[g + 4*r][j] * x;
    }
    #pragma unroll
    for (int r = 0; r < 4; r++) {
        int i = i0 + g + 4*r;
        out[((size_t)b * Nn + i) * 128 + 64 + f] = acc[r];
    }
}

// ---------------- launcher --------------------------------------------------
extern "C" void kernel_launch(void* const* d_in, const int* in_sizes, int n_in,
                              void* d_out, int out_size)
{
    const float* node_fea = (const float*)d_in[0];
    const float* edge_fea = (const float*)d_in[1];
    const int*   eidx     = (const int*)  d_in[2];
    const float* dis      = (const float*)d_in[3];
    const float* Wn = (const float*)d_in[4];
    const float* bn = (const float*)d_in[5];
    const float* We = (const float*)d_in[6];
    const float* be = (const float*)d_in[7];
    const float* Wc[3] = {(const float*)d_in[8],  (const float*)d_in[11], (const float*)d_in[14]};
    const float* bc[3] = {(const float*)d_in[9],  (const float*)d_in[12], (const float*)d_in[15]};
    const float* ac[3] = {(const float*)d_in[10], (const float*)d_in[13], (const float*)d_in[16]};
    const float* Wf  = (const float*)d_in[17];
    const float* bf  = (const float*)d_in[18];
    const float* DAw = (const float*)d_in[19];
    const float* DAb = (const float*)d_in[20];
    float* out = (float*)d_out;

    float *nfA, *nfB, *SG, *WfT, *bfo;
    cudaGetSymbolAddress((void**)&nfA, g_nfA);
    cudaGetSymbolAddress((void**)&nfB, g_nfB);
    cudaGetSymbolAddress((void**)&SG,  g_SG);
    cudaGetSymbolAddress((void**)&WfT, g_WfoldT);
    cudaGetSymbolAddress((void**)&bfo, g_bfold);

    const int smem_edge = (KE*256 + KE*128 + 256) * 4 + 128 * 4;  // 64512 B
    cudaFuncSetAttribute(edge_conv_kernel,
                         cudaFuncAttributeMaxDynamicSharedMemorySize, smem_edge);

    // weight folds (tiny)
    for (int i = 0; i < 3; i++)
        fold_kernel<<<1, 256>>>(We, be, Wc[i], bc[i], WfT + i*KE*256, bfo + i*256);

    // nf0 = node_fea @ Wn.T + bn
    gemm64_kernel<<<dim3(NFD/64, (Bb*Nn)/64), 256>>>(
        node_fea, ONF_, Wn, ONF_, bn, nfA, NFD, ONF_);

    float* cur = nfA;
    float* nxt = nfB;
    for (int i = 0; i < 3; i++) {
        // S = nf @ W[:, :128].T  (into SG[:, 0:256))
        gemm64_kernel<<<dim3(4, (Bb*Nn)/64), 256>>>(
            cur, NFD, Wc[i], 320, (const float*)nullptr, SG, 512, NFD);
        // G = nf @ W[:, 128:256].T  (into SG[:, 256:512))
        gemm64_kernel<<<dim3(4, (Bb*Nn)/64), 256>>>(
            cur, NFD, Wc[i] + 128, 320, (const float*)nullptr, SG + 256, 512, NFD);
        // fused edge gating + aggregation + softplus
        edge_conv_kernel<<<dim3(Nn/8, Bb), 256, smem_edge>>>(
            edge_fea, eidx, SG, WfT + i*KE*256, bfo + i*256, cur, ac[i], nxt);
        float* t = cur; cur = nxt; nxt = t;
    }

    // fin = nf @ Wf.T + bf  -> out[...,:64]
    gemm64_kernel<<<dim3(1, (Bb*Nn)/64), 256>>>(
        cur, NFD, Wf, NFD, bf, out, 128, NFD);

    // node1 = DA @ fin -> out[...,64:]
    final_mix_kernel<<<dim3(Nn/16, Bb), 256>>>(dis, DAw, DAb, out);
}

// round 8
// speedup vs baseline: 1.6012x; 1.6012x over previous
#include <cuda_runtime.h>
#include <math.h>

#define Bb   64
#define Nn   256
#define Mm   16
#define ONF_ 92
#define KE   41      // OEF
#define NFD  128
#define EFD  64

typedef unsigned long long u64;

// ---- packed f32x2 helpers (sm_103a FFMA2) ----------------------------------
#define FMA2(d, a, b, c) \
    asm("fma.rn.f32x2 %0, %1, %2, %3;" : "=l"(d) : "l"(a), "l"(b), "l"(c))

__device__ __forceinline__ u64 dup2(float x) {
    u64 r; unsigned xi = __float_as_uint(x);
    asm("mov.b64 %0, {%1, %1};" : "=l"(r) : "r"(xi));
    return r;
}
__device__ __forceinline__ float2 unpack2(u64 v) {
    unsigned lo, hi;
    asm("mov.b64 {%0, %1}, %2;" : "=r"(lo), "=r"(hi) : "l"(v));
    return make_float2(__uint_as_float(lo), __uint_as_float(hi));
}

// ---------------- scratch (static device globals; no allocs) ----------------
__device__ float g_nfA[Bb*Nn*NFD];                 // 8.4 MB
__device__ float g_nfB[Bb*Nn*NFD];                 // 8.4 MB
__device__ float g_SG[(size_t)Bb*Nn*512];          // 33.5 MB (S [0,256), G [256,512))
__device__ float g_WfoldT[3*KE*256];               // folded edge weights per conv
__device__ float g_bfold[3*256];                   // folded bias per conv
__device__ float g_WSG[3*512*128];                 // packed S|G weights per conv

__device__ __forceinline__ float softplusf_(float x) {
    return (x > 15.f) ? x : __logf(1.f + __expf(x));
}
__device__ __forceinline__ float sigmoidf_(float x) {
    return __fdividef(1.f, 1.f + __expf(-x));
}

// ---------------- fold: per conv i (blockIdx.x), build WfoldT/bfold/WSG -----
__global__ void fold_kernel(const float* __restrict__ We,   // [64][41]
                            const float* __restrict__ be,   // [64]
                            const float* __restrict__ W0, const float* __restrict__ b0,
                            const float* __restrict__ W1, const float* __restrict__ b1,
                            const float* __restrict__ W2, const float* __restrict__ b2,
                            float* __restrict__ WfT_all,
                            float* __restrict__ bf_all,
                            float* __restrict__ WSG_all)
{
    int ci = blockIdx.x;
    const float* W = (ci == 0) ? W0 : (ci == 1) ? W1 : W2;
    const float* b = (ci == 0) ? b0 : (ci == 1) ? b1 : b2;
    float* WfoldT = WfT_all + ci * KE * 256;
    float* bfold  = bf_all  + ci * 256;
    float* wsg    = WSG_all + ci * 512 * 128;

    __shared__ float Wes[EFD][KE];
    __shared__ float bes[EFD];
    int tid = threadIdx.x;   // 256
    for (int i = tid; i < EFD*KE; i += 256) Wes[i/KE][i%KE] = We[i];
    if (tid < EFD) bes[tid] = be[tid];
    __syncthreads();

    int o = tid;
    const float* wr = &W[o*320 + 256];
    float bf = b[o];
    #pragma unroll 4
    for (int j = 0; j < EFD; j++) bf += wr[j] * bes[j];
    bfold[o] = bf;
    for (int k = 0; k < KE; k++) {
        float s = 0.f;
        #pragma unroll 4
        for (int j = 0; j < EFD; j++) s += wr[j] * Wes[j][k];
        WfoldT[k*256 + o] = s;
    }
    // pack WSG[512][128]: rows 0..255 = W[o][0:128], rows 256..511 = W[o-256][128:256]
    for (int t = tid; t < 512*128; t += 256) {
        int oo = t >> 7, k = t & 127;
        wsg[t] = (oo < 256) ? W[oo*320 + k] : W[(oo-256)*320 + 128 + k];
    }
}

// ---------------- fp32 GEMM, f32x2 inner, double-buffered smem --------------
// C[r][o] = sum_k X[r][k]*W[o][k] + b[o]; tile 64x64, 256 thr, 4x4 microtile.
__global__ __launch_bounds__(256) void gemm64_kernel(
    const float* __restrict__ X, int ldx,
    const float* __restrict__ W, int ldw,
    const float* __restrict__ bias,
    float* __restrict__ C, int ldc, int K)
{
    __shared__ float Xs[2][16][64];
    __shared__ float Ws[2][16][64];
    int tid = threadIdx.x;
    int rb = blockIdx.y * 64, ob = blockIdx.x * 64;
    int lr = tid >> 2;            // 0..63
    int lk = (tid & 3) * 4;       // 0,4,8,12
    int tr = tid >> 4;            // 0..15
    int tc = tid & 15;            // 0..15

    u64 acc[4][2];
    #pragma unroll
    for (int i = 0; i < 4; i++) { acc[i][0] = 0ull; acc[i][1] = 0ull; }

    const float* Xrow = X + (size_t)(rb + lr) * ldx;
    const float* Wrow = W + (size_t)(ob + lr) * ldw;

    #pragma unroll
    for (int j = 0; j < 4; j++) {
        int k = lk + j;
        Xs[0][lk+j][lr] = (k < K) ? Xrow[k] : 0.f;
        Ws[0][lk+j][lr] = (k < K) ? Wrow[k] : 0.f;
    }
    __syncthreads();

    int nch = (K + 15) >> 4;
    for (int c = 0; c < nch; c++) {
        int cur = c & 1;
        float px[4], pw[4];
        bool more = (c + 1 < nch);
        if (more) {
            #pragma unroll
            for (int j = 0; j < 4; j++) {
                int k = (c+1)*16 + lk + j;
                px[j] = (k < K) ? Xrow[k] : 0.f;
                pw[j] = (k < K) ? Wrow[k] : 0.f;
            }
        }
        #pragma unroll
        for (int kk = 0; kk < 16; kk++) {
            float4 xv = *(const float4*)&Xs[cur][kk][4*tr];
            const u64* wp = (const u64*)&Ws[cur][kk][4*tc];
            u64 w0 = wp[0], w1 = wp[1];
            u64 x0 = dup2(xv.x), x1 = dup2(xv.y), x2 = dup2(xv.z), x3 = dup2(xv.w);
            FMA2(acc[0][0], x0, w0, acc[0][0]); FMA2(acc[0][1], x0, w1, acc[0][1]);
            FMA2(acc[1][0], x1, w0, acc[1][0]); FMA2(acc[1][1], x1, w1, acc[1][1]);
            FMA2(acc[2][0], x2, w0, acc[2][0]); FMA2(acc[2][1], x2, w1, acc[2][1]);
            FMA2(acc[3][0], x3, w0, acc[3][0]); FMA2(acc[3][1], x3, w1, acc[3][1]);
        }
        if (more) {
            int nxt = cur ^ 1;
            #pragma unroll
            for (int j = 0; j < 4; j++) {
                Xs[nxt][lk+j][lr] = px[j];
                Ws[nxt][lk+j][lr] = pw[j];
            }
            __syncthreads();
        }
    }

    float bb[4] = {0.f, 0.f, 0.f, 0.f};
    if (bias) {
        float4 t = *(const float4*)&bias[ob + 4*tc];
        bb[0] = t.x; bb[1] = t.y; bb[2] = t.z; bb[3] = t.w;
    }
    #pragma unroll
    for (int i = 0; i < 4; i++) {
        float2 p0 = unpack2(acc[i][0]);
        float2 p1 = unpack2(acc[i][1]);
        float4 v = make_float4(p0.x + bb[0], p0.y + bb[1], p1.x + bb[2], p1.y + bb[3]);
        *(float4*)&C[(size_t)(rb + 4*tr + i) * ldc + ob + 4*tc] = v;
    }
}

// ---------------- fused edge conv kernel (f32x2 inner) ----------------------
// block: 8 nodes of one batch = 128 edges. Per thread: 8 edges x (4F + 4C outs),
// two passes (node groups).
__global__ __launch_bounds__(256) void edge_conv_kernel(
    const float* __restrict__ edge_fea,  // [B,N,M,41]
    const int*   __restrict__ eidx,      // [B,N,M]
    const float* __restrict__ SG,        // [B,N,512]
    const float* __restrict__ WfoldT,    // [41][256]
    const float* __restrict__ bfold,     // [256]
    const float* __restrict__ nf_in,     // [B,N,128]
    const float* __restrict__ alpha_p,
    float* __restrict__ nf_out)          // [B,N,128]
{
    extern __shared__ float smem[];
    float* WT  = smem;                    // 41*256
    float* Et  = smem + KE*256;           // 41*128
    float* bia = Et + KE*128;             // 256
    int*   nbs = (int*)(bia + 256);       // 128

    int tid = threadIdx.x;
    int b   = blockIdx.y;
    int n0  = blockIdx.x * 8;
    int bn0 = b * Nn + n0;

    {
        const float4* src = (const float4*)WfoldT;
        float4* dst = (float4*)WT;
        for (int i = tid; i < KE*64; i += 256) dst[i] = src[i];
    }
    bia[tid] = bfold[tid];
    if (tid < 128) nbs[tid] = eidx[bn0 * Mm + tid];
    {
        const float* ep = edge_fea + (size_t)bn0 * Mm * KE;
        for (int i = tid; i < 128*KE; i += 256) {
            int e = i / KE, k = i - e * KE;
            Et[k*128 + e] = ep[i];
        }
    }
    __syncthreads();

    float alpha = *alpha_p;
    int half = tid & 1;
    int pg   = (tid >> 1) & 31;
    int tlb  = tid >> 6;          // 0..3
    int o0   = pg * 4;

    for (int p = 0; p < 2; p++) {
        int tl = tlb + 4*p;            // node within block 0..7
        int e0 = tl*16 + half*8;       // first of this thread's 8 edges

        int nbr[8];
        #pragma unroll
        for (int j = 0; j < 8; j++) nbr[j] = nbs[e0 + j];

        u64 acc2[8][4];
        #pragma unroll
        for (int j = 0; j < 8; j++)
            #pragma unroll
            for (int q = 0; q < 4; q++) acc2[j][q] = 0ull;

        #pragma unroll 2
        for (int k = 0; k < KE; k++) {
            const float* er = &Et[k*128 + e0];
            float4 xa = *(const float4*)er;
            float4 xb = *(const float4*)(er + 4);
            const u64* wrf = (const u64*)&WT[k*256 + o0];
            const u64* wrc = (const u64*)&WT[k*256 + o0 + 128];
            u64 wf0 = wrf[0], wf1 = wrf[1];
            u64 wc0 = wrc[0], wc1 = wrc[1];
            u64 xd[8];
            xd[0]=dup2(xa.x); xd[1]=dup2(xa.y); xd[2]=dup2(xa.z); xd[3]=dup2(xa.w);
            xd[4]=dup2(xb.x); xd[5]=dup2(xb.y); xd[6]=dup2(xb.z); xd[7]=dup2(xb.w);
            #pragma unroll
            for (int j = 0; j < 8; j++) {
                FMA2(acc2[j][0], xd[j], wf0, acc2[j][0]);
                FMA2(acc2[j][1], xd[j], wf1, acc2[j][1]);
                FMA2(acc2[j][2], xd[j], wc0, acc2[j][2]);
                FMA2(acc2[j][3], xd[j], wc1, acc2[j][3]);
            }
        }

        int bn = b * Nn + (n0 + tl);
        const float* Srow = SG + (size_t)bn * 512;
        float4 Sa = *(const float4*)&Srow[o0];
        float4 Sc = *(const float4*)&Srow[o0 + 128];
        float4 ba = *(const float4*)&bia[o0];
        float4 bc = *(const float4*)&bia[o0 + 128];
        float sf[4] = {Sa.x + ba.x, Sa.y + ba.y, Sa.z + ba.z, Sa.w + ba.w};
        float sc[4] = {Sc.x + bc.x, Sc.y + bc.y, Sc.z + bc.z, Sc.w + bc.w};

        float sums[4] = {0.f, 0.f, 0.f, 0.f};
        #pragma unroll
        for (int j = 0; j < 8; j++) {
            int nb = nbr[j];
            float mask = (nb >= 0) ? 1.f : 0.f;
            if (nb < 0) nb = 0;
            const float* Grow = SG + ((size_t)(b * Nn + nb)) * 512 + 256;
            float4 Ga = *(const float4*)&Grow[o0];
            float4 Gc = *(const float4*)&Grow[o0 + 128];
            float2 f01 = unpack2(acc2[j][0]);
            float2 f23 = unpack2(acc2[j][1]);
            float2 c01 = unpack2(acc2[j][2]);
            float2 c23 = unpack2(acc2[j][3]);
            float gfv[4] = {f01.x + Ga.x, f01.y + Ga.y, f23.x + Ga.z, f23.y + Ga.w};
            float gcv[4] = {c01.x + Gc.x, c01.y + Gc.y, c23.x + Gc.z, c23.y + Gc.w};
            #pragma unroll
            for (int q = 0; q < 4; q++) {
                float gf = gfv[q] + sf[q];
                float gc = gcv[q] + sc[q];
                float filt = mask * sigmoidf_(gf);
                float core = softplusf_(gc);
                sums[q] += filt * core;
            }
        }
        #pragma unroll
        for (int q = 0; q < 4; q++)
            sums[q] += __shfl_xor_sync(0xffffffffu, sums[q], 1);

        if (half == 0) {
            const float* nin = nf_in + (size_t)bn * NFD + o0;
            float4 nv = *(const float4*)nin;
            float4 ov;
            ov.x = softplusf_(alpha * nv.x + sums[0]);
            ov.y = softplusf_(alpha * nv.y + sums[1]);
            ov.z = softplusf_(alpha * nv.z + sums[2]);
            ov.w = softplusf_(alpha * nv.w + sums[3]);
            *(float4*)&nf_out[(size_t)bn * NFD + o0] = ov;
        }
    }
}

// ---------------- final: node1 = sigmoid(DAw*dis+DAb) @ fin ----------------
__global__ __launch_bounds__(256) void final_mix_kernel(
    const float* __restrict__ dis,
    const float* __restrict__ DAw_p,
    const float* __restrict__ DAb_p,
    float* __restrict__ out)
{
    __shared__ float DAs[16][256];
    int b  = blockIdx.y;
    int i0 = blockIdx.x * 16;
    float daw = *DAw_p, dab = *DAb_p;
    for (int t = threadIdx.x; t < 16*256; t += 256) {
        int ii = t >> 8, j = t & 255;
        DAs[ii][j] = sigmoidf_(daw * dis[(i0 + ii) * Nn + j] + dab);
    }
    __syncthreads();

    int f = threadIdx.x & 63;
    int g = threadIdx.x >> 6;   // 0..3
    float acc[4] = {0.f, 0.f, 0.f, 0.f};
    const float* fin = out + (size_t)b * Nn * 128;
    for (int j = 0; j < Nn; j++) {
        float x = fin[(size_t)j * 128 + f];
        #pragma unroll
        for (int r = 0; r < 4; r++) acc[r] += DAs[g + 4*r][j] * x;
    }
    #pragma unroll
    for (int r = 0; r < 4; r++) {
        int i = i0 + g + 4*r;
        out[((size_t)b * Nn + i) * 128 + 64 + f] = acc[r];
    }
}

// ---------------- launcher --------------------------------------------------
extern "C" void kernel_launch(void* const* d_in, const int* in_sizes, int n_in,
                              void* d_out, int out_size)
{
    const float* node_fea = (const float*)d_in[0];
    const float* edge_fea = (const float*)d_in[1];
    const int*   eidx     = (const int*)  d_in[2];
    const float* dis      = (const float*)d_in[3];
    const float* Wn = (const float*)d_in[4];
    const float* bn = (const float*)d_in[5];
    const float* We = (const float*)d_in[6];
    const float* be = (const float*)d_in[7];
    const float* Wc[3] = {(const float*)d_in[8],  (const float*)d_in[11], (const float*)d_in[14]};
    const float* bc[3] = {(const float*)d_in[9],  (const float*)d_in[12], (const float*)d_in[15]};
    const float* ac[3] = {(const float*)d_in[10], (const float*)d_in[13], (const float*)d_in[16]};
    const float* Wf  = (const float*)d_in[17];
    const float* bf  = (const float*)d_in[18];
    const float* DAw = (const float*)d_in[19];
    const float* DAb = (const float*)d_in[20];
    float* out = (float*)d_out;

    float *nfA, *nfB, *SG, *WfT, *bfo, *WSG;
    cudaGetSymbolAddress((void**)&nfA, g_nfA);
    cudaGetSymbolAddress((void**)&nfB, g_nfB);
    cudaGetSymbolAddress((void**)&SG,  g_SG);
    cudaGetSymbolAddress((void**)&WfT, g_WfoldT);
    cudaGetSymbolAddress((void**)&bfo, g_bfold);
    cudaGetSymbolAddress((void**)&WSG, g_WSG);

    const int smem_edge = (KE*256 + KE*128 + 256) * 4 + 128 * 4;  // 64512 B
    cudaFuncSetAttribute(edge_conv_kernel,
                         cudaFuncAttributeMaxDynamicSharedMemorySize, smem_edge);

    // weight folds for all 3 convs in one launch
    fold_kernel<<<3, 256>>>(We, be, Wc[0], bc[0], Wc[1], bc[1], Wc[2], bc[2],
                            WfT, bfo, WSG);

    // nf0 = node_fea @ Wn.T + bn
    gemm64_kernel<<<dim3(NFD/64, (Bb*Nn)/64), 256>>>(
        node_fea, ONF_, Wn, ONF_, bn, nfA, NFD, ONF_);

    float* cur = nfA;
    float* nxt = nfB;
    for (int i = 0; i < 3; i++) {
        // S|G = nf @ WSG.T  (512-wide, single launch)
        gemm64_kernel<<<dim3(8, (Bb*Nn)/64), 256>>>(
            cur, NFD, WSG + i*512*128, NFD, (const float*)nullptr, SG, 512, NFD);
        // fused edge gating + aggregation + softplus
        edge_conv_kernel<<<dim3(Nn/8, Bb), 256, smem_edge>>>(
            edge_fea, eidx, SG, WfT + i*KE*256, bfo + i*256, cur, ac[i], nxt);
        float* t = cur; cur = nxt; nxt = t;
    }

    // fin = nf @ Wf.T + bf  -> out[...,:64]
    gemm64_kernel<<<dim3(1, (Bb*Nn)/64), 256>>>(
        cur, NFD, Wf, NFD, bf, out, 128, NFD);

    // node1 = DA @ fin -> out[...,64:]
    final_mix_kernel<<<dim3(Nn/16, Bb), 256>>>(dis, DAw, DAb, out);
}

// round 12
// speedup vs baseline: 1.7071x; 1.0661x over previous
#include <cuda_runtime.h>
#include <math.h>

#define Bb   64
#define Nn   256
#define Mm   16
#define ONF_ 92
#define KE   41      // OEF
#define NFD  128
#define EFD  64

typedef unsigned long long u64;

// ---- packed f32x2 helpers (sm_103a FFMA2) ----------------------------------
#define FMA2(d, a, b, c) \
    asm("fma.rn.f32x2 %0, %1, %2, %3;" : "=l"(d) : "l"(a), "l"(b), "l"(c))

__device__ __forceinline__ u64 dup2(float x) {
    u64 r; unsigned xi = __float_as_uint(x);
    asm("mov.b64 %0, {%1, %1};" : "=l"(r) : "r"(xi));
    return r;
}
__device__ __forceinline__ float2 unpack2(u64 v) {
    unsigned lo, hi;
    asm("mov.b64 {%0, %1}, %2;" : "=r"(lo), "=r"(hi) : "l"(v));
    return make_float2(__uint_as_float(lo), __uint_as_float(hi));
}

// ---------------- scratch (static device globals; no allocs) ----------------
__device__ float g_nfA[Bb*Nn*NFD];
__device__ float g_nfB[Bb*Nn*NFD];
__device__ float g_SG[(size_t)Bb*Nn*512];          // S [0,256), G [256,512)
__device__ float g_WfoldT[3*KE*256];
__device__ float g_bfold[3*256];
__device__ float g_WSG[3*512*128];

__device__ __forceinline__ float softplusf_(float x) {
    return (x > 15.f) ? x : __logf(1.f + __expf(x));
}
__device__ __forceinline__ float sigmoidf_(float x) {
    return __fdividef(1.f, 1.f + __expf(-x));
}

// ---------------- fold: per conv (blockIdx.x) build WfoldT/bfold/WSG --------
__global__ void fold_kernel(const float* __restrict__ We,   // [64][41]
                            const float* __restrict__ be,   // [64]
                            const float* __restrict__ W0, const float* __restrict__ b0,
                            const float* __restrict__ W1, const float* __restrict__ b1,
                            const float* __restrict__ W2, const float* __restrict__ b2,
                            float* __restrict__ WfT_all,
                            float* __restrict__ bf_all,
                            float* __restrict__ WSG_all)
{
    int ci = blockIdx.x;
    const float* W = (ci == 0) ? W0 : (ci == 1) ? W1 : W2;
    const float* b = (ci == 0) ? b0 : (ci == 1) ? b1 : b2;
    float* WfoldT = WfT_all + ci * KE * 256;
    float* bfold  = bf_all  + ci * 256;
    float* wsg    = WSG_all + ci * 512 * 128;

    __shared__ float Wes[EFD][KE];
    __shared__ float bes[EFD];
    int tid = threadIdx.x;   // 256
    for (int i = tid; i < EFD*KE; i += 256) Wes[i/KE][i%KE] = We[i];
    if (tid < EFD) bes[tid] = be[tid];
    __syncthreads();

    int o = tid;
    const float* wr = &W[o*320 + 256];
    float bf = b[o];
    #pragma unroll 4
    for (int j = 0; j < EFD; j++) bf += wr[j] * bes[j];
    bfold[o] = bf;
    for (int k = 0; k < KE; k++) {
        float s = 0.f;
        #pragma unroll 4
        for (int j = 0; j < EFD; j++) s += wr[j] * Wes[j][k];
        WfoldT[k*256 + o] = s;
    }
    for (int t = tid; t < 512*128; t += 256) {
        int oo = t >> 7, k = t & 127;
        wsg[t] = (oo < 256) ? W[oo*320 + k] : W[(oo-256)*320 + 128 + k];
    }
}

// ---------------- gemm128: 128x128 tile, K multiple of 8, ldx=ldw=128 -------
// C[r][o] = sum_k X[r][k]*W[o][k] (+bias). X duplicated in smem -> pure
// LDS.128 + FFMA2 inner loop (no dup movs).
__global__ __launch_bounds__(256, 2) void gemm128_kernel(
    const float* __restrict__ X,     // [R,128]
    const float* __restrict__ W,     // [O,128]
    const float* __restrict__ bias,  // [O] or null
    float* __restrict__ C, int ldc, int K)
{
    __shared__ float Xs2[2][8][256];   // duplicated rows
    __shared__ float Ws[2][8][128];

    int tid = threadIdx.x;
    int rb = blockIdx.y * 128, ob = blockIdx.x * 128;
    int lr = tid >> 1;        // 0..127
    int hf = tid & 1;         // k-half of chunk
    int tr = tid >> 4;        // 0..15
    int tc = tid & 15;        // 0..15

    const float* Xrow = X + (size_t)(rb + lr) * 128 + hf*4;
    const float* Wrow = W + (size_t)(ob + lr) * 128 + hf*4;

    u64 acc[8][4];
    #pragma unroll
    for (int i = 0; i < 8; i++)
        #pragma unroll
        for (int q = 0; q < 4; q++) acc[i][q] = 0ull;

    // load chunk 0
    float4 xv = *(const float4*)Xrow;
    float4 wv = *(const float4*)Wrow;
    {
        u64* xd = (u64*)&Xs2[0][hf*4][2*lr];
        // write rows hf*4+j with stride of one k-row (256 floats)
        *(u64*)&Xs2[0][hf*4+0][2*lr] = dup2(xv.x);
        *(u64*)&Xs2[0][hf*4+1][2*lr] = dup2(xv.y);
        *(u64*)&Xs2[0][hf*4+2][2*lr] = dup2(xv.z);
        *(u64*)&Xs2[0][hf*4+3][2*lr] = dup2(xv.w);
        Ws[0][hf*4+0][lr] = wv.x;
        Ws[0][hf*4+1][lr] = wv.y;
        Ws[0][hf*4+2][lr] = wv.z;
        Ws[0][hf*4+3][lr] = wv.w;
        (void)xd;
    }
    __syncthreads();

    int nch = K >> 3;
    for (int c = 0; c < nch; c++) {
        int cur = c & 1;
        float4 px, pw;
        bool more = (c + 1 < nch);
        if (more) {
            px = *(const float4*)(Xrow + (c+1)*8);
            pw = *(const float4*)(Wrow + (c+1)*8);
        }
        #pragma unroll
        for (int k = 0; k < 8; k++) {
            const ulonglong2* xp = (const ulonglong2*)&Xs2[cur][k][16*tr];
            const ulonglong2* wp = (const ulonglong2*)&Ws[cur][k][8*tc];
            ulonglong2 x01 = xp[0], x23 = xp[1], x45 = xp[2], x67 = xp[3];
            ulonglong2 wA = wp[0], wB = wp[1];
            u64 xd[8] = {x01.x, x01.y, x23.x, x23.y, x45.x, x45.y, x67.x, x67.y};
            u64 w0 = wA.x, w1 = wA.y, w2 = wB.x, w3 = wB.y;
            #pragma unroll
            for (int i = 0; i < 8; i++) {
                FMA2(acc[i][0], xd[i], w0, acc[i][0]);
                FMA2(acc[i][1], xd[i], w1, acc[i][1]);
                FMA2(acc[i][2], xd[i], w2, acc[i][2]);
                FMA2(acc[i][3], xd[i], w3, acc[i][3]);
            }
        }
        if (more) {
            int nxt = cur ^ 1;
            *(u64*)&Xs2[nxt][hf*4+0][2*lr] = dup2(px.x);
            *(u64*)&Xs2[nxt][hf*4+1][2*lr] = dup2(px.y);
            *(u64*)&Xs2[nxt][hf*4+2][2*lr] = dup2(px.z);
            *(u64*)&Xs2[nxt][hf*4+3][2*lr] = dup2(px.w);
            Ws[nxt][hf*4+0][lr] = pw.x;
            Ws[nxt][hf*4+1][lr] = pw.y;
            Ws[nxt][hf*4+2][lr] = pw.z;
            Ws[nxt][hf*4+3][lr] = pw.w;
            __syncthreads();
        }
    }

    float bb[8] = {0,0,0,0,0,0,0,0};
    if (bias) {
        float4 t0 = *(const float4*)&bias[ob + 8*tc];
        float4 t1 = *(const float4*)&bias[ob + 8*tc + 4];
        bb[0]=t0.x; bb[1]=t0.y; bb[2]=t0.z; bb[3]=t0.w;
        bb[4]=t1.x; bb[5]=t1.y; bb[6]=t1.z; bb[7]=t1.w;
    }
    #pragma unroll
    for (int i = 0; i < 8; i++) {
        int r = rb + 8*tr + i;
        float2 p0 = unpack2(acc[i][0]);
        float2 p1 = unpack2(acc[i][1]);
        float2 p2 = unpack2(acc[i][2]);
        float2 p3 = unpack2(acc[i][3]);
        float4 v0 = make_float4(p0.x+bb[0], p0.y+bb[1], p1.x+bb[2], p1.y+bb[3]);
        float4 v1 = make_float4(p2.x+bb[4], p2.y+bb[5], p3.x+bb[6], p3.y+bb[7]);
        *(float4*)&C[(size_t)r * ldc + ob + 8*tc]     = v0;
        *(float4*)&C[(size_t)r * ldc + ob + 8*tc + 4] = v1;
    }
}

// ---------------- fp32 GEMM 64x64 (kept for K=92 / O=64 cases) --------------
__global__ __launch_bounds__(256) void gemm64_kernel(
    const float* __restrict__ X, int ldx,
    const float* __restrict__ W, int ldw,
    const float* __restrict__ bias,
    float* __restrict__ C, int ldc, int K)
{
    __shared__ float Xs[2][16][64];
    __shared__ float Ws[2][16][64];
    int tid = threadIdx.x;
    int rb = blockIdx.y * 64, ob = blockIdx.x * 64;
    int lr = tid >> 2;
    int lk = (tid & 3) * 4;
    int tr = tid >> 4;
    int tc = tid & 15;

    u64 acc[4][2];
    #pragma unroll
    for (int i = 0; i < 4; i++) { acc[i][0] = 0ull; acc[i][1] = 0ull; }

    const float* Xrow = X + (size_t)(rb + lr) * ldx;
    const float* Wrow = W + (size_t)(ob + lr) * ldw;

    #pragma unroll
    for (int j = 0; j < 4; j++) {
        int k = lk + j;
        Xs[0][lk+j][lr] = (k < K) ? Xrow[k] : 0.f;
        Ws[0][lk+j][lr] = (k < K) ? Wrow[k] : 0.f;
    }
    __syncthreads();

    int nch = (K + 15) >> 4;
    for (int c = 0; c < nch; c++) {
        int cur = c & 1;
        float px[4], pw[4];
        bool more = (c + 1 < nch);
        if (more) {
            #pragma unroll
            for (int j = 0; j < 4; j++) {
                int k = (c+1)*16 + lk + j;
                px[j] = (k < K) ? Xrow[k] : 0.f;
                pw[j] = (k < K) ? Wrow[k] : 0.f;
            }
        }
        #pragma unroll
        for (int kk = 0; kk < 16; kk++) {
            float4 xv = *(const float4*)&Xs[cur][kk][4*tr];
            const u64* wp = (const u64*)&Ws[cur][kk][4*tc];
            u64 w0 = wp[0], w1 = wp[1];
            u64 x0 = dup2(xv.x), x1 = dup2(xv.y), x2 = dup2(xv.z), x3 = dup2(xv.w);
            FMA2(acc[0][0], x0, w0, acc[0][0]); FMA2(acc[0][1], x0, w1, acc[0][1]);
            FMA2(acc[1][0], x1, w0, acc[1][0]); FMA2(acc[1][1], x1, w1, acc[1][1]);
            FMA2(acc[2][0], x2, w0, acc[2][0]); FMA2(acc[2][1], x2, w1, acc[2][1]);
            FMA2(acc[3][0], x3, w0, acc[3][0]); FMA2(acc[3][1], x3, w1, acc[3][1]);
        }
        if (more) {
            int nxt = cur ^ 1;
            #pragma unroll
            for (int j = 0; j < 4; j++) {
                Xs[nxt][lk+j][lr] = px[j];
                Ws[nxt][lk+j][lr] = pw[j];
            }
            __syncthreads();
        }
    }

    float bb[4] = {0.f, 0.f, 0.f, 0.f};
    if (bias) {
        float4 t = *(const float4*)&bias[ob + 4*tc];
        bb[0] = t.x; bb[1] = t.y; bb[2] = t.z; bb[3] = t.w;
    }
    #pragma unroll
    for (int i = 0; i < 4; i++) {
        float2 p0 = unpack2(acc[i][0]);
        float2 p1 = unpack2(acc[i][1]);
        float4 v = make_float4(p0.x + bb[0], p0.y + bb[1], p1.x + bb[2], p1.y + bb[3]);
        *(float4*)&C[(size_t)(rb + 4*tr + i) * ldc + ob + 4*tc] = v;
    }
}

// ---------------- fused edge conv kernel (f32x2 inner) ----------------------
__global__ __launch_bounds__(256) void edge_conv_kernel(
    const float* __restrict__ edge_fea,  // [B,N,M,41]
    const int*   __restrict__ eidx,      // [B,N,M]
    const float* __restrict__ SG,        // [B,N,512]
    const float* __restrict__ WfoldT,    // [41][256]
    const float* __restrict__ bfold,     // [256]
    const float* __restrict__ nf_in,     // [B,N,128]
    const float* __restrict__ alpha_p,
    float* __restrict__ nf_out)          // [B,N,128]
{
    extern __shared__ float smem[];
    float* WT  = smem;                    // 41*256
    float* Et  = smem + KE*256;           // 41*128
    float* bia = Et + KE*128;             // 256
    int*   nbs = (int*)(bia + 256);       // 128

    int tid = threadIdx.x;
    int b   = blockIdx.y;
    int n0  = blockIdx.x * 8;
    int bn0 = b * Nn + n0;

    {
        const float4* src = (const float4*)WfoldT;
        float4* dst = (float4*)WT;
        for (int i = tid; i < KE*64; i += 256) dst[i] = src[i];
    }
    bia[tid] = bfold[tid];
    if (tid < 128) nbs[tid] = eidx[bn0 * Mm + tid];
    {
        const float* ep = edge_fea + (size_t)bn0 * Mm * KE;
        for (int i = tid; i < 128*KE; i += 256) {
            int e = i / KE, k = i - e * KE;
            Et[k*128 + e] = ep[i];
        }
    }
    __syncthreads();

    float alpha = *alpha_p;
    int half = tid & 1;
    int pg   = (tid >> 1) & 31;
    int tlb  = tid >> 6;          // 0..3
    int o0   = pg * 4;

    for (int p = 0; p < 2; p++) {
        int tl = tlb + 4*p;            // node within block 0..7
        int e0 = tl*16 + half*8;       // first of this thread's 8 edges

        int nbr[8];
        #pragma unroll
        for (int j = 0; j < 8; j++) nbr[j] = nbs[e0 + j];

        u64 acc2[8][4];
        #pragma unroll
        for (int j = 0; j < 8; j++)
            #pragma unroll
            for (int q = 0; q < 4; q++) acc2[j][q] = 0ull;

        const float* etp = &Et[e0];
        const float* wtp = &WT[o0];
        #pragma unroll 4
        for (int k = 0; k < KE; k++, etp += 128, wtp += 256) {
            float4 xa = *(const float4*)etp;
            float4 xb = *(const float4*)(etp + 4);
            const u64* wrf = (const u64*)wtp;
            const u64* wrc = (const u64*)(wtp + 128);
            u64 wf0 = wrf[0], wf1 = wrf[1];
            u64 wc0 = wrc[0], wc1 = wrc[1];
            u64 xd[8];
            xd[0]=dup2(xa.x); xd[1]=dup2(xa.y); xd[2]=dup2(xa.z); xd[3]=dup2(xa.w);
            xd[4]=dup2(xb.x); xd[5]=dup2(xb.y); xd[6]=dup2(xb.z); xd[7]=dup2(xb.w);
            #pragma unroll
            for (int j = 0; j < 8; j++) {
                FMA2(acc2[j][0], xd[j], wf0, acc2[j][0]);
                FMA2(acc2[j][1], xd[j], wf1, acc2[j][1]);
                FMA2(acc2[j][2], xd[j], wc0, acc2[j][2]);
                FMA2(acc2[j][3], xd[j], wc1, acc2[j][3]);
            }
        }

        int bn = b * Nn + (n0 + tl);
        const float* Srow = SG + (size_t)bn * 512;
        float4 Sa = *(const float4*)&Srow[o0];
        float4 Sc = *(const float4*)&Srow[o0 + 128];
        float4 ba = *(const float4*)&bia[o0];
        float4 bc = *(const float4*)&bia[o0 + 128];
        float sf[4] = {Sa.x + ba.x, Sa.y + ba.y, Sa.z + ba.z, Sa.w + ba.w};
        float sc[4] = {Sc.x + bc.x, Sc.y + bc.y, Sc.z + bc.z, Sc.w + bc.w};

        float sums[4] = {0.f, 0.f, 0.f, 0.f};
        #pragma unroll
        for (int j = 0; j < 8; j++) {
            int nb = nbr[j];
            float mask = (nb >= 0) ? 1.f : 0.f;
            if (nb < 0) nb = 0;
            const float* Grow = SG + ((size_t)(b * Nn + nb)) * 512 + 256;
            float4 Ga = *(const float4*)&Grow[o0];
            float4 Gc = *(const float4*)&Grow[o0 + 128];
            float2 f01 = unpack2(acc2[j][0]);
            float2 f23 = unpack2(acc2[j][1]);
            float2 c01 = unpack2(acc2[j][2]);
            float2 c23 = unpack2(acc2[j][3]);
            float gfv[4] = {f01.x + Ga.x, f01.y + Ga.y, f23.x + Ga.z, f23.y + Ga.w};
            float gcv[4] = {c01.x + Gc.x, c01.y + Gc.y, c23.x + Gc.z, c23.y + Gc.w};
            #pragma unroll
            for (int q = 0; q < 4; q++) {
                float gf = gfv[q] + sf[q];
                float gc = gcv[q] + sc[q];
                float filt = mask * sigmoidf_(gf);
                float core = softplusf_(gc);
                sums[q] += filt * core;
            }
        }
        #pragma unroll
        for (int q = 0; q < 4; q++)
            sums[q] += __shfl_xor_sync(0xffffffffu, sums[q], 1);

        if (half == 0) {
            const float* nin = nf_in + (size_t)bn * NFD + o0;
            float4 nv = *(const float4*)nin;
            float4 ov;
            ov.x = softplusf_(alpha * nv.x + sums[0]);
            ov.y = softplusf_(alpha * nv.y + sums[1]);
            ov.z = softplusf_(alpha * nv.z + sums[2]);
            ov.w = softplusf_(alpha * nv.w + sums[3]);
            *(float4*)&nf_out[(size_t)bn * NFD + o0] = ov;
        }
    }
}

// ---------------- final: node1 = sigmoid(DAw*dis+DAb) @ fin ----------------
__global__ __launch_bounds__(256) void final_mix_kernel(
    const float* __restrict__ dis,
    const float* __restrict__ DAw_p,
    const float* __restrict__ DAb_p,
    float* __restrict__ out)
{
    __shared__ float DAs[16][256];
    int b  = blockIdx.y;
    int i0 = blockIdx.x * 16;
    float daw = *DAw_p, dab = *DAb_p;
    for (int t = threadIdx.x; t < 16*256; t += 256) {
        int ii = t >> 8, j = t & 255;
        DAs[ii][j] = sigmoidf_(daw * dis[(i0 + ii) * Nn + j] + dab);
    }
    __syncthreads();

    int f = threadIdx.x & 63;
    int g = threadIdx.x >> 6;   // 0..3
    float acc[4] = {0.f, 0.f, 0.f, 0.f};
    const float* fin = out + (size_t)b * Nn * 128;
    for (int j = 0; j < Nn; j++) {
        float x = fin[(size_t)j * 128 + f];
        #pragma unroll
        for (int r = 0; r < 4; r++) acc[r] += DAs[g + 4*r][j] * x;
    }
    #pragma unroll
    for (int r = 0; r < 4; r++) {
        int i = i0 + g + 4*r;
        out[((size_t)b * Nn + i) * 128 + 64 + f] = acc[r];
    }
}

// ---------------- launcher --------------------------------------------------
extern "C" void kernel_launch(void* const* d_in, const int* in_sizes, int n_in,
                              void* d_out, int out_size)
{
    const float* node_fea = (const float*)d_in[0];
    const float* edge_fea = (const float*)d_in[1];
    const int*   eidx     = (const int*)  d_in[2];
    const float* dis      = (const float*)d_in[3];
    const float* Wn = (const float*)d_in[4];
    const float* bn = (const float*)d_in[5];
    const float* We = (const float*)d_in[6];
    const float* be = (const float*)d_in[7];
    const float* Wc[3] = {(const float*)d_in[8],  (const float*)d_in[11], (const float*)d_in[14]};
    const float* bc[3] = {(const float*)d_in[9],  (const float*)d_in[12], (const float*)d_in[15]};
    const float* ac[3] = {(const float*)d_in[10], (const float*)d_in[13], (const float*)d_in[16]};
    const float* Wf  = (const float*)d_in[17];
    const float* bf  = (const float*)d_in[18];
    const float* DAw = (const float*)d_in[19];
    const float* DAb = (const float*)d_in[20];
    float* out = (float*)d_out;

    float *nfA, *nfB, *SG, *WfT, *bfo, *WSG;
    cudaGetSymbolAddress((void**)&nfA, g_nfA);
    cudaGetSymbolAddress((void**)&nfB, g_nfB);
    cudaGetSymbolAddress((void**)&SG,  g_SG);
    cudaGetSymbolAddress((void**)&WfT, g_WfoldT);
    cudaGetSymbolAddress((void**)&bfo, g_bfold);
    cudaGetSymbolAddress((void**)&WSG, g_WSG);

    const int smem_edge = (KE*256 + KE*128 + 256) * 4 + 128 * 4;  // 64512 B
    cudaFuncSetAttribute(edge_conv_kernel,
                         cudaFuncAttributeMaxDynamicSharedMemorySize, smem_edge);

    fold_kernel<<<3, 256>>>(We, be, Wc[0], bc[0], Wc[1], bc[1], Wc[2], bc[2],
                            WfT, bfo, WSG);

    // nf0 = node_fea @ Wn.T + bn   (K=92 -> gemm64 path)
    gemm64_kernel<<<dim3(NFD/64, (Bb*Nn)/64), 256>>>(
        node_fea, ONF_, Wn, ONF_, bn, nfA, NFD, ONF_);

    float* cur = nfA;
    float* nxt = nfB;
    for (int i = 0; i < 3; i++) {
        // S|G = nf @ WSG.T  (16384x512, K=128) via gemm128
        gemm128_kernel<<<dim3(512/128, (Bb*Nn)/128), 256>>>(
            cur, WSG + i*512*128, (const float*)nullptr, SG, 512, NFD);
        edge_conv_kernel<<<dim3(Nn/8, Bb), 256, smem_edge>>>(
            edge_fea, eidx, SG, WfT + i*KE*256, bfo + i*256, cur, ac[i], nxt);
        float* t = cur; cur = nxt; nxt = t;
    }

    // fin = nf @ Wf.T + bf -> out[...,:64]  (O=64 -> gemm64 path)
    gemm64_kernel<<<dim3(1, (Bb*Nn)/64), 256>>>(
        cur, NFD, Wf, NFD, bf, out, 128, NFD);

    final_mix_kernel<<<dim3(Nn/16, Bb), 256>>>(dis, DAw, DAb, out);
}